// round 7
// baseline (speedup 1.0000x reference)
#include <cuda_runtime.h>
#include <cuda_bf16.h>
#include <cstdint>

#define NN 2000
#define EE 32000
#define BB 8
#define TT 12
#define CIN 32
#define FCH 64
#define TBm 96
#define ROWLEN 3072

typedef unsigned long long ull;
typedef unsigned short u16;

// ---------------- warp MMA helpers (sm_80-era PTX, valid on compute_103) ------
__device__ __forceinline__ uint32_t smem_u32(const void* p) {
    uint32_t a;
    asm("{ .reg .u64 t; cvta.to.shared.u64 t, %1; cvt.u32.u64 %0, t; }" : "=r"(a) : "l"(p));
    return a;
}
__device__ __forceinline__ void ldsm4(uint32_t* r, uint32_t addr) {
    asm volatile("ldmatrix.sync.aligned.m8n8.x4.shared.b16 {%0,%1,%2,%3}, [%4];"
        : "=r"(r[0]), "=r"(r[1]), "=r"(r[2]), "=r"(r[3]) : "r"(addr));
}
__device__ __forceinline__ void ldsm2(uint32_t* r, uint32_t addr) {
    asm volatile("ldmatrix.sync.aligned.m8n8.x2.shared.b16 {%0,%1}, [%2];"
        : "=r"(r[0]), "=r"(r[1]) : "r"(addr));
}
__device__ __forceinline__ void mma16816(float* d, const uint32_t* a, const uint32_t* b) {
    asm volatile(
        "mma.sync.aligned.m16n8k16.row.col.f32.bf16.bf16.f32 "
        "{%0,%1,%2,%3}, {%4,%5,%6,%7}, {%8,%9}, {%0,%1,%2,%3};"
        : "+f"(d[0]), "+f"(d[1]), "+f"(d[2]), "+f"(d[3])
        : "r"(a[0]), "r"(a[1]), "r"(a[2]), "r"(a[3]), "r"(b[0]), "r"(b[1]));
}
// split fp32 pair -> packed bf16x2 (hi, lo)
__device__ __forceinline__ void split2(float x, float y, uint32_t& h, uint32_t& l) {
    __nv_bfloat16 hx = __float2bfloat16(x), hy = __float2bfloat16(y);
    __nv_bfloat16 lx = __float2bfloat16(x - __bfloat162float(hx));
    __nv_bfloat16 ly = __float2bfloat16(y - __bfloat162float(hy));
    h = ((uint32_t)__bfloat16_as_ushort(hy) << 16) | (uint32_t)__bfloat16_as_ushort(hx);
    l = ((uint32_t)__bfloat16_as_ushort(ly) << 16) | (uint32_t)__bfloat16_as_ushort(lx);
}
__device__ __forceinline__ void split1(float x, u16& h, u16& l) {
    __nv_bfloat16 hx = __float2bfloat16(x);
    __nv_bfloat16 lx = __float2bfloat16(x - __bfloat162float(hx));
    h = __bfloat16_as_ushort(hx); l = __bfloat16_as_ushort(lx);
}

// ---------------- scratch ----------------
__device__ float g_x0[NN*ROWLEN];
__device__ float g_y1[NN*ROWLEN];
__device__ float g_z2[NN*ROWLEN];
__device__ float g_out[NN*TBm*FCH];
__device__ float g_deg[NN];
__device__ int   g_cnt[NN];
__device__ int   g_rowptr[NN+1];
__device__ int   g_cursor[NN];
__device__ float g_selfw[NN];
__device__ int   g_col[EE];
__device__ float g_wval[EE];
// prebuilt bf16 hi/lo weight images: [n(=f)][k] with padded strides
__device__ u16 g_Bch_h[64*104];
__device__ u16 g_Bch_l[64*104];
__device__ u16 g_Bep_h[64*232];
__device__ u16 g_Bep_l[64*232];

// ---------------- CSR build (R1) ----------------
__global__ void k_zero() {
    int i = blockIdx.x*blockDim.x + threadIdx.x;
    if (i < NN) { g_cnt[i] = 0; g_deg[i] = 0.f; }
}
__global__ void k_count(const int* __restrict__ ei, const float* __restrict__ ew) {
    int e = blockIdx.x*blockDim.x + threadIdx.x;
    if (e < EE) {
        atomicAdd(&g_cnt[ei[EE + e]], 1);
        atomicAdd(&g_deg[ei[e]], ew[e]);
    }
}
__global__ void k_scan(const float* __restrict__ lmax) {
    __shared__ int sa[2048], sb[2048];
    int tid = threadIdx.x;
    for (int i = tid; i < 2048; i += 1024) sa[i] = (i < NN) ? g_cnt[i] : 0;
    __syncthreads();
    int* src = sa; int* dst = sb;
    for (int off = 1; off < 2048; off <<= 1) {
        for (int i = tid; i < 2048; i += 1024)
            dst[i] = src[i] + ((i >= off) ? src[i - off] : 0);
        __syncthreads();
        int* tp = src; src = dst; dst = tp;
    }
    float alpha = 2.0f / lmax[0];
    for (int i = tid; i < NN; i += 1024) {
        g_rowptr[i+1] = src[i];
        g_cursor[i]   = (i == 0) ? 0 : src[i-1];
        g_selfw[i]    = alpha * g_deg[i] - 1.0f;
    }
    if (tid == 0) g_rowptr[0] = 0;
}
__global__ void k_scatter(const int* __restrict__ ei, const float* __restrict__ ew,
                          const float* __restrict__ lmax) {
    int e = blockIdx.x*blockDim.x + threadIdx.x;
    if (e < EE) {
        int s = ei[e], d = ei[EE + e];
        int pos = atomicAdd(&g_cursor[d], 1);
        float alpha = 2.0f / lmax[0];
        g_col[pos]  = s;
        g_wval[pos] = -alpha * ew[e] - ((s == d) ? 1.0f : 0.0f);
    }
}

// ---------------- x0 materialization (R1) ----------------
__global__ void k_x0(const float* __restrict__ X) {
    __shared__ float s[32*97];
    int n2 = blockIdx.x;
    int tid = threadIdx.x;
    for (int i = tid; i < ROWLEN; i += 256) {
        int u = n2*ROWLEN + i;
        int c   = u / 192000;       int rem  = u - c*192000;
        int b   = rem / 24000;      int rem2 = rem - b*24000;
        int n   = rem2 / 12;        int t    = rem2 - n*12;
        int c2 = i / 96, m = i - c2*96;
        s[c2*97 + m] = X[((b*NN + n)*CIN + c)*TT + t];
    }
    __syncthreads();
    for (int i = tid; i < ROWLEN; i += 256) {
        int m = i >> 5, c2 = i & 31;
        g_x0[n2*ROWLEN + i] = s[c2*97 + m];
    }
}

// ---------------- graph propagation (R1) ----------------
__global__ void k_prop(int mode) {
    const float* in  = (mode == 1) ? g_x0 : g_y1;
    float*       out = (mode == 1) ? g_y1 : g_z2;
    int n = blockIdx.y;
    int f = blockIdx.x*768 + threadIdx.x;
    int beg = g_rowptr[n], end = g_rowptr[n+1];
    float sw = g_selfw[n];
    const float* r = in + (size_t)n*ROWLEN;
    float a0 = sw*r[f], a1 = sw*r[f+256], a2 = sw*r[f+512];
    for (int e = beg; e < end; e++) {
        int s = g_col[e]; float w = g_wval[e];
        const float* rs = in + (size_t)s*ROWLEN;
        a0 += w*rs[f]; a1 += w*rs[f+256]; a2 += w*rs[f+512];
    }
    size_t o = (size_t)n*ROWLEN + f;
    if (mode == 1) {
        out[o] = a0; out[o+256] = a1; out[o+512] = a2;
    } else {
        out[o]     = 2.f*a0 - g_x0[o];
        out[o+256] = 2.f*a1 - g_x0[o+256];
        out[o+512] = 2.f*a2 - g_x0[o+512];
    }
}

// ---------------- weight image prep ----------------
__global__ void k_prepB(const float* __restrict__ wcheb, const float* __restrict__ tw,
                        const float* __restrict__ rw) {
    int i = blockIdx.x*blockDim.x + threadIdx.x;
    if (i < 6144) {                       // cheb: B[f][k] = wcheb[k*64+f]
        int f = i & 63, k = i >> 6;
        u16 h, l; split1(wcheb[i], h, l);
        g_Bch_h[f*104 + k] = h; g_Bch_l[f*104 + k] = l;
    } else if (i < 6144 + 14336) {        // epi: B[f][k]: k<192 tw, else rw
        int j = i - 6144;
        int f = j / 224, k = j - f*224;
        float v = (k < 192) ? tw[f*192 + k] : rw[f*32 + (k - 192)];
        u16 h, l; split1(v, h, l);
        g_Bep_h[f*232 + k] = h; g_Bep_l[f*232 + k] = l;
    }
}

// ---------------- Cheb GEMM: relu([x0|y1|z2] @ Wcheb + b) -> g_out -----------
// 128 rows/CTA, 256 thr (8 warps, 16 rows each). SMEM bf16 A/B hi+lo, padded strides.
#define CH_AH 0
#define CH_AL 26624
#define CH_BH 53248
#define CH_BL 66560
#define CH_BIAS 79872
#define CH_SMEM (79872 + 256)
__global__ __launch_bounds__(256)
void k_cheb(const float* __restrict__ bcheb) {
    extern __shared__ char smem[];
    u16* Ah = (u16*)(smem + CH_AH);
    u16* Al = (u16*)(smem + CH_AL);
    float* bias_s = (float*)(smem + CH_BIAS);
    int tid = threadIdx.x, w = tid >> 5, lane = tid & 31;
    int row0 = blockIdx.x * 128;

    // stage A (fp32 -> hi/lo bf16), rows [row0, row0+128), k: 0-31 x0, 32-63 y1, 64-95 z2
    for (int i4 = tid; i4 < 3072; i4 += 256) {
        int r = i4 / 24, q = i4 - r*24;
        size_t m = (size_t)(row0 + r) * 32;
        float4 v = (q < 8)  ? ((const float4*)(g_x0 + m))[q]
                 : (q < 16) ? ((const float4*)(g_y1 + m))[q - 8]
                            : ((const float4*)(g_z2 + m))[q - 16];
        uint32_t h0, l0, h1, l1;
        split2(v.x, v.y, h0, l0);
        split2(v.z, v.w, h1, l1);
        int k0 = q * 4;
        *(uint2*)&Ah[r*104 + k0] = make_uint2(h0, h1);
        *(uint2*)&Al[r*104 + k0] = make_uint2(l0, l1);
    }
    // copy prebuilt B images (flat uint4)
    {
        uint4* bh = (uint4*)(smem + CH_BH);
        uint4* bl = (uint4*)(smem + CH_BL);
        const uint4* gh = (const uint4*)g_Bch_h;
        const uint4* gl = (const uint4*)g_Bch_l;
        for (int i = tid; i < 832; i += 256) { bh[i] = gh[i]; bl[i] = gl[i]; }
    }
    if (tid < 64) bias_s[tid] = bcheb[tid];
    __syncthreads();

    // per-warp MMA: rows r0 = w*16, full N=64 (8 n-tiles), K=96 (6 k-steps)
    float d[8][4];
    #pragma unroll
    for (int nt = 0; nt < 8; nt++) { d[nt][0]=0.f; d[nt][1]=0.f; d[nt][2]=0.f; d[nt][3]=0.f; }

    int r0 = w*16;
    int a_mat = lane >> 3, a_rin = lane & 7;
    int a_row = r0 + a_rin + (a_mat & 1)*8;
    uint32_t aAh = smem_u32(&Ah[a_row*104]) + (a_mat >> 1)*16;
    uint32_t aAl = aAh + (CH_AL - CH_AH);
    int bl16 = lane & 15;
    uint32_t bOff = (uint32_t)(((bl16 & 7)*104 + (bl16 >> 3)*8) * 2);
    uint32_t aBh = smem_u32(smem + CH_BH) + bOff;
    uint32_t aBl = aBh + (CH_BL - CH_BH);

    #pragma unroll
    for (int ks = 0; ks < 6; ks++) {
        uint32_t ah[4], al[4];
        ldsm4(ah, aAh + ks*32);
        ldsm4(al, aAl + ks*32);
        #pragma unroll
        for (int nt = 0; nt < 8; nt++) {
            uint32_t bh[2], blr[2];
            uint32_t ba = (uint32_t)(nt*8*208) + ks*32;
            ldsm2(bh,  aBh + ba);
            ldsm2(blr, aBl + ba);
            mma16816(d[nt], ah, bh);
            mma16816(d[nt], ah, blr);
            mma16816(d[nt], al, bh);
        }
    }

    // epilogue: bias + relu -> g_out
    int qrow = lane >> 2, qc = lane & 3;
    int ra = row0 + r0 + qrow, rb = ra + 8;
    #pragma unroll
    for (int nt = 0; nt < 8; nt++) {
        int c0 = nt*8 + qc*2;
        float b0 = bias_s[c0], b1 = bias_s[c0+1];
        *(float2*)&g_out[(size_t)ra*64 + c0] =
            make_float2(fmaxf(d[nt][0] + b0, 0.f), fmaxf(d[nt][1] + b1, 0.f));
        *(float2*)&g_out[(size_t)rb*64 + c0] =
            make_float2(fmaxf(d[nt][2] + b0, 0.f), fmaxf(d[nt][3] + b1, 0.f));
    }
}

// ---------------- Epi: im2col GEMM + bias + relu + LayerNorm + store ----------
// 1 CTA per node. 192 thr (6 warps = 6 row-tiles of 16; rows r = b*12+t, 96 rows).
// K = 224: k<192 -> temporal conv (fc,j), k>=192 -> residual (c). 14 k-steps.
#define EP_AH 0
#define EP_AL 44544
#define EP_BH 89088
#define EP_BL 118784
#define EP_XC 148480
#define EP_XS 173440
#define EP_AUX 185760
#define EP_SMEM (185760 + 768)
__global__ __launch_bounds__(192)
void k_epi(const float* __restrict__ X,  const float* __restrict__ tb,
           const float* __restrict__ rb, const float* __restrict__ lg,
           const float* __restrict__ lb, float* __restrict__ O) {
    extern __shared__ char smem[];
    u16* Ah = (u16*)(smem + EP_AH);
    u16* Al = (u16*)(smem + EP_AL);
    float* Xc_s   = (float*)(smem + EP_XC);   // [96][65]; aliased as zs after mma
    float* Xs     = (float*)(smem + EP_XS);   // [8][385]
    float* bias_s = (float*)(smem + EP_AUX);
    float* lg_s   = bias_s + 64;
    float* lb_s   = lg_s + 64;
    int tid = threadIdx.x, w = tid >> 5, lane = tid & 31;
    int n = blockIdx.x;

    // stage B (flat uint4 copy of prebuilt images)
    {
        uint4* bh = (uint4*)(smem + EP_BH);
        uint4* bl = (uint4*)(smem + EP_BL);
        const uint4* gh = (const uint4*)g_Bep_h;
        const uint4* gl = (const uint4*)g_Bep_l;
        for (int i = tid; i < 1856; i += 192) { bh[i] = gh[i]; bl[i] = gl[i]; }
    }
    // stage Xc: g_out rows [n*96, n*96+96) -> [96][65]
    {
        const float4* src = (const float4*)(g_out + (size_t)n*TBm*64);
        for (int i4 = tid; i4 < 1536; i4 += 192) {
            float4 v = src[i4];
            int r = i4 >> 4, f0 = (i4 & 15) * 4;
            float* dst = &Xc_s[r*65 + f0];
            dst[0] = v.x; dst[1] = v.y; dst[2] = v.z; dst[3] = v.w;
        }
    }
    // stage Xs: raw X rows for this node, all 8 batches
    for (int i = tid; i < 3072; i += 192) {
        int bb = i / 384, q = i - bb*384;
        Xs[bb*385 + q] = X[((size_t)(bb*NN + n))*384 + q];
    }
    if (tid < 64) { bias_s[tid] = tb[tid] + rb[tid]; lg_s[tid] = lg[tid]; lb_s[tid] = lb[tid]; }
    __syncthreads();

    // im2col build: thread = (row r = tid>>1, half = tid&1 -> k in [half*112, half*112+112))
    {
        int r = tid >> 1, half = tid & 1;
        int b = r / 12, t = r - b*12;
        int kb = half * 112, ke = kb + 112;
        int fc = kb / 3, j3 = kb - fc*3;
        const float* xcrow = &Xc_s[b*12*65];
        const float* xsrow = &Xs[b*385];
        u16* ahp = &Ah[r*232];
        u16* alp = &Al[r*232];
        for (int k = kb; k < ke; k++) {
            float v;
            if (k < 192) {
                int tt = t + j3 - 1;
                v = ((unsigned)tt < 12u) ? xcrow[tt*65 + fc] : 0.f;
                if (++j3 == 3) { j3 = 0; fc++; }
            } else {
                v = xsrow[(k - 192)*12 + t];
            }
            u16 h, l; split1(v, h, l);
            ahp[k] = h; alp[k] = l;
        }
    }
    __syncthreads();

    // MMA: warp w handles rows [w*16, w*16+16), all 64 cols, K=224
    float d[8][4];
    #pragma unroll
    for (int nt = 0; nt < 8; nt++) { d[nt][0]=0.f; d[nt][1]=0.f; d[nt][2]=0.f; d[nt][3]=0.f; }

    int r0 = w*16;
    int a_mat = lane >> 3, a_rin = lane & 7;
    int a_row = r0 + a_rin + (a_mat & 1)*8;
    uint32_t aAh = smem_u32(&Ah[a_row*232]) + (a_mat >> 1)*16;
    uint32_t aAl = aAh + (EP_AL - EP_AH);
    int bl16 = lane & 15;
    uint32_t bOff = (uint32_t)(((bl16 & 7)*232 + (bl16 >> 3)*8) * 2);
    uint32_t aBh = smem_u32(smem + EP_BH) + bOff;
    uint32_t aBl = aBh + (EP_BL - EP_BH);

    #pragma unroll 2
    for (int ks = 0; ks < 14; ks++) {
        uint32_t ah[4], al[4];
        ldsm4(ah, aAh + ks*32);
        ldsm4(al, aAl + ks*32);
        #pragma unroll
        for (int nt = 0; nt < 8; nt++) {
            uint32_t bh[2], blr[2];
            uint32_t ba = (uint32_t)(nt*8*464) + ks*32;
            ldsm2(bh,  aBh + ba);
            ldsm2(blr, aBl + ba);
            mma16816(d[nt], ah, bh);
            mma16816(d[nt], ah, blr);
            mma16816(d[nt], al, bh);
        }
    }

    // bias + relu in-place, then in-register LayerNorm over 64 cols per row
    int qrow = lane >> 2, qc = lane & 3;
    float sa = 0.f, qa = 0.f, sb = 0.f, qb = 0.f;
    #pragma unroll
    for (int nt = 0; nt < 8; nt++) {
        int c0 = nt*8 + qc*2;
        float b0 = bias_s[c0], b1 = bias_s[c0+1];
        d[nt][0] = fmaxf(d[nt][0] + b0, 0.f);
        d[nt][1] = fmaxf(d[nt][1] + b1, 0.f);
        d[nt][2] = fmaxf(d[nt][2] + b0, 0.f);
        d[nt][3] = fmaxf(d[nt][3] + b1, 0.f);
        sa += d[nt][0] + d[nt][1];  qa += d[nt][0]*d[nt][0] + d[nt][1]*d[nt][1];
        sb += d[nt][2] + d[nt][3];  qb += d[nt][2]*d[nt][2] + d[nt][3]*d[nt][3];
    }
    #pragma unroll
    for (int o = 1; o <= 2; o <<= 1) {
        sa += __shfl_xor_sync(0xffffffffu, sa, o);
        qa += __shfl_xor_sync(0xffffffffu, qa, o);
        sb += __shfl_xor_sync(0xffffffffu, sb, o);
        qb += __shfl_xor_sync(0xffffffffu, qb, o);
    }
    float mua = sa * (1.f/64.f), mub = sb * (1.f/64.f);
    float rsa = rsqrtf(qa * (1.f/64.f) - mua*mua + 1e-5f);
    float rsb = rsqrtf(qb * (1.f/64.f) - mub*mub + 1e-5f);

    float* zs = Xc_s;   // alias: all Xc_s reads finished before the mma sync
    int ra = r0 + qrow, rbv = ra + 8;
    #pragma unroll
    for (int nt = 0; nt < 8; nt++) {
        int c0 = nt*8 + qc*2;
        zs[ra*65 + c0]    = (d[nt][0] - mua)*rsa*lg_s[c0]   + lb_s[c0];
        zs[ra*65 + c0+1]  = (d[nt][1] - mua)*rsa*lg_s[c0+1] + lb_s[c0+1];
        zs[rbv*65 + c0]   = (d[nt][2] - mub)*rsb*lg_s[c0]   + lb_s[c0];
        zs[rbv*65 + c0+1] = (d[nt][3] - mub)*rsb*lg_s[c0+1] + lb_s[c0+1];
    }
    __syncthreads();

    // coalesced output: O[b][n][f][t]
    for (int i = tid; i < 6144; i += 192) {
        int bb = i / 768, q = i - bb*768;
        int f = q / 12, to = q - f*12;
        O[((size_t)(bb*NN + n))*768 + q] = zs[(bb*12 + to)*65 + f];
    }
}

// ---------------- launch ----------------
extern "C" void kernel_launch(void* const* d_in, const int* in_sizes, int n_in,
                              void* d_out, int out_size) {
    const float* X     = (const float*)d_in[0];
    const int*   ei    = (const int*)  d_in[1];
    const float* ew    = (const float*)d_in[2];
    const float* lmax  = (const float*)d_in[3];
    const float* wcheb = (const float*)d_in[4];
    const float* bcheb = (const float*)d_in[5];
    const float* tw    = (const float*)d_in[6];
    const float* tb    = (const float*)d_in[7];
    const float* rw    = (const float*)d_in[8];
    const float* rb    = (const float*)d_in[9];
    const float* lng   = (const float*)d_in[10];
    const float* lnb   = (const float*)d_in[11];
    float* O = (float*)d_out;

    cudaFuncSetAttribute(k_cheb, cudaFuncAttributeMaxDynamicSharedMemorySize, CH_SMEM);
    cudaFuncSetAttribute(k_epi,  cudaFuncAttributeMaxDynamicSharedMemorySize, EP_SMEM);

    k_zero   <<<8,   256>>>();
    k_count  <<<125, 256>>>(ei, ew);
    k_prepB  <<<80,  256>>>(wcheb, tw, rw);
    k_scan   <<<1,  1024>>>(lmax);
    k_scatter<<<125, 256>>>(ei, ew, lmax);
    k_x0     <<<2000,256>>>(X);
    k_prop   <<<dim3(4,2000),256>>>(1);
    k_prop   <<<dim3(4,2000),256>>>(2);
    k_cheb   <<<1500,256,CH_SMEM>>>(bcheb);
    k_epi    <<<2000,192,EP_SMEM>>>(X, tb, rb, lng, lnb, O);
}

// round 8
// speedup vs baseline: 1.3479x; 1.3479x over previous
#include <cuda_runtime.h>

#define NN 2000
#define EE 32000
#define BB 8
#define TT 12
#define CIN 32
#define FCH 64
#define TBm 96        // T*B flattened "batch" dim
#define ROWLEN 3072   // TBm*CIN floats per node

// ---------------- scratch (static device globals; no allocation) ----------------
__device__ float g_x0[NN*ROWLEN];
__device__ float g_y1[NN*ROWLEN];
__device__ float g_z2[NN*ROWLEN];
__device__ float g_out[NN*TBm*FCH];
__device__ float g_deg[NN];
__device__ int   g_cnt[NN];
__device__ int   g_rowptr[NN+1];
__device__ int   g_cursor[NN];
__device__ float g_selfw[NN];
__device__ int   g_col[EE];
__device__ float g_wval[EE];
__device__ float g_twg[64*64*4];   // Winograd-transformed temporal weights [(fc*64+f)*4 + i]

// ---------------- CSR build ----------------
__global__ void k_zero() {
    int i = blockIdx.x*blockDim.x + threadIdx.x;
    if (i < NN) { g_cnt[i] = 0; g_deg[i] = 0.f; }
}

__global__ void k_count(const int* __restrict__ ei, const float* __restrict__ ew) {
    int e = blockIdx.x*blockDim.x + threadIdx.x;
    if (e < EE) {
        atomicAdd(&g_cnt[ei[EE + e]], 1);       // in-degree count over dst
        atomicAdd(&g_deg[ei[e]], ew[e]);        // weighted degree over src (PyG)
    }
}

__global__ void k_scan(const float* __restrict__ lmax) {
    __shared__ int sa[2048], sb[2048];
    int tid = threadIdx.x;
    for (int i = tid; i < 2048; i += 1024) sa[i] = (i < NN) ? g_cnt[i] : 0;
    __syncthreads();
    int* src = sa; int* dst = sb;
    for (int off = 1; off < 2048; off <<= 1) {
        for (int i = tid; i < 2048; i += 1024)
            dst[i] = src[i] + ((i >= off) ? src[i - off] : 0);
        __syncthreads();
        int* tp = src; src = dst; dst = tp;
    }
    float alpha = 2.0f / lmax[0];
    for (int i = tid; i < NN; i += 1024) {
        g_rowptr[i+1] = src[i];
        g_cursor[i]   = (i == 0) ? 0 : src[i-1];
        g_selfw[i]    = alpha * g_deg[i] - 1.0f;   // appended self-loop: 2*deg/lmax - 1
    }
    if (tid == 0) g_rowptr[0] = 0;
}

__global__ void k_scatter(const int* __restrict__ ei, const float* __restrict__ ew,
                          const float* __restrict__ lmax) {
    int e = blockIdx.x*blockDim.x + threadIdx.x;
    if (e < EE) {
        int s = ei[e], d = ei[EE + e];
        int pos = atomicAdd(&g_cursor[d], 1);
        float alpha = 2.0f / lmax[0];
        g_col[pos]  = s;
        g_wval[pos] = -alpha * ew[e] - ((s == d) ? 1.0f : 0.0f);
    }
}

// ---------------- Winograd weight transform: gt = [w0, (w0+w1+w2)/2, (w0-w1+w2)/2, w2]
__global__ void k_prepW(const float* __restrict__ tw) {
    int i = blockIdx.x*blockDim.x + threadIdx.x;
    if (i < 4096) {
        int fc = i >> 6, f = i & 63;
        float w0 = tw[f*192 + fc*3 + 0];
        float w1 = tw[f*192 + fc*3 + 1];
        float w2 = tw[f*192 + fc*3 + 2];
        float s = w0 + w2;
        float4 g = make_float4(w0, 0.5f*(s + w1), 0.5f*(s - w1), w2);
        ((float4*)g_twg)[fc*64 + f] = g;
    }
}

// ---------------- x0 materialization (faithful buggy permute+reshape) ----------------
__global__ void k_x0(const float* __restrict__ X) {
    __shared__ float s[32*97];
    int n2 = blockIdx.x;
    int tid = threadIdx.x;
    for (int i = tid; i < ROWLEN; i += 256) {
        int u = n2*ROWLEN + i;
        int c   = u / 192000;       int rem  = u - c*192000;
        int b   = rem / 24000;      int rem2 = rem - b*24000;
        int n   = rem2 / 12;        int t    = rem2 - n*12;
        int c2 = i / 96, m = i - c2*96;
        s[c2*97 + m] = X[((b*NN + n)*CIN + c)*TT + t];
    }
    __syncthreads();
    for (int i = tid; i < ROWLEN; i += 256) {
        int m = i >> 5, c2 = i & 31;
        g_x0[n2*ROWLEN + i] = s[c2*97 + m];
    }
}

// ---------------- graph propagation (CSR gather, no atomics) ----------------
__global__ void k_prop(int mode) {
    const float* in  = (mode == 1) ? g_x0 : g_y1;
    float*       out = (mode == 1) ? g_y1 : g_z2;
    int n = blockIdx.y;
    int f = blockIdx.x*768 + threadIdx.x;
    int beg = g_rowptr[n], end = g_rowptr[n+1];
    float sw = g_selfw[n];
    const float* r = in + (size_t)n*ROWLEN;
    float a0 = sw*r[f], a1 = sw*r[f+256], a2 = sw*r[f+512];
    for (int e = beg; e < end; e++) {
        int s = g_col[e]; float w = g_wval[e];
        const float* rs = in + (size_t)s*ROWLEN;
        a0 += w*rs[f]; a1 += w*rs[f+256]; a2 += w*rs[f+512];
    }
    size_t o = (size_t)n*ROWLEN + f;
    if (mode == 1) {
        out[o] = a0; out[o+256] = a1; out[o+512] = a2;
    } else {
        out[o]     = 2.f*a0 - g_x0[o];
        out[o+256] = 2.f*a1 - g_x0[o+256];
        out[o+512] = 2.f*a2 - g_x0[o+512];
    }
}

// ---------------- Chebyshev contraction (R1-exact): relu([x0|y1|z2] @ W + b) --------
__global__ void k_gemm(const float* __restrict__ wcheb, const float* __restrict__ bcheb) {
    extern __shared__ float sm[];
    float* As = sm;            // [64 rows][96 k]
    float* Ws = sm + 64*96;    // [96 k][64 f]
    int row0 = blockIdx.x * 64;
    int tid = threadIdx.x;
    for (int i = tid; i < 96*64; i += 256) Ws[i] = wcheb[i];
    for (int i = tid; i < 64*96; i += 256) {
        int r = i / 96, c = i - r*96;
        const float* src = (c < 32) ? g_x0 : ((c < 64) ? g_y1 : g_z2);
        As[i] = src[(size_t)(row0 + r)*32 + (c & 31)];
    }
    __syncthreads();
    int tx = tid & 15, ty = tid >> 4;   // 16x16 thread grid, 4x4 per thread
    float acc[4][4] = {};
    #pragma unroll 8
    for (int c = 0; c < 96; c++) {
        float4 w4 = reinterpret_cast<float4*>(Ws)[c*16 + tx];
        #pragma unroll
        for (int k = 0; k < 4; k++) {
            float av = As[(ty*4 + k)*96 + c];
            acc[k][0] += av*w4.x; acc[k][1] += av*w4.y;
            acc[k][2] += av*w4.z; acc[k][3] += av*w4.w;
        }
    }
    const float4 bb4 = reinterpret_cast<const float4*>(bcheb)[tx];
    #pragma unroll
    for (int k = 0; k < 4; k++) {
        int row = row0 + ty*4 + k;
        float4 o;
        o.x = fmaxf(acc[k][0] + bb4.x, 0.f);
        o.y = fmaxf(acc[k][1] + bb4.y, 0.f);
        o.z = fmaxf(acc[k][2] + bb4.z, 0.f);
        o.w = fmaxf(acc[k][3] + bb4.w, 0.f);
        reinterpret_cast<float4*>(g_out + (size_t)row*64)[tx] = o;
    }
}

// ---------------- fused Winograd temporal conv + residual + relu + LN + output ------
// block = (b, 8 nodes), 512 threads: thread = (f = tid&63, ng = tid>>6)
// SMEM floats:
//   dts [8 ng][64 fc][6 p][4]  @0      (12288)  Winograd input transforms (warp-broadcast)
//   xcT [8 ng][fc*12+t]        @12288  (6144)   staging; aliased as zb after conv
//   xs  [8 ng][c*12+t]         @18432  (3072)
//   rws [32 c][65]             @21504  (2080)
//   tbrb/lg/lb [64]x3, mu/rs [96]x2    (576)
#define EPI_SMEM ((12288 + 6144 + 3072 + 2080 + 576) * 4)
__global__ __launch_bounds__(512, 2)
void k_epi(const float* __restrict__ X,  const float* __restrict__ tb,
           const float* __restrict__ rw, const float* __restrict__ rb,
           const float* __restrict__ lg, const float* __restrict__ lb,
           float* __restrict__ O) {
    extern __shared__ float sm[];
    float* dts  = sm;
    float* xcT  = sm + 12288;
    float* xs   = sm + 18432;
    float* rws  = sm + 21504;
    float* tbrb = sm + 23584;
    float* lg_s = tbrb + 64;
    float* lb_s = lg_s + 64;
    float* mu_s = lb_s + 64;
    float* rs_s = mu_s + 96;

    int b  = blockIdx.y;
    int n0 = blockIdx.x * 8;
    int tid = threadIdx.x;

    // stage xcT from g_out (coalesced reads, as R1)
    for (int i = tid; i < 6144; i += 512) {
        int ng = i / 768, j = i - ng*768;
        int t = j >> 6, fc = j & 63;
        xcT[ng*768 + fc*12 + t] = g_out[((size_t)(n0 + ng)*TBm + b*TT)*64 + j];
    }
    // stage raw X
    for (int i = tid; i < 3072; i += 512) {
        int ng = i / 384, j = i - ng*384;
        xs[i] = X[((size_t)(b*NN + n0 + ng)*CIN)*TT + j];
    }
    // rws[c*65 + f] = rw[f*32 + c]
    for (int i = tid; i < 2048; i += 512) {
        int f = i >> 5, c = i & 31;
        rws[c*65 + f] = rw[i];
    }
    if (tid < 64) { tbrb[tid] = tb[tid] + rb[tid]; lg_s[tid] = lg[tid]; lb_s[tid] = lb[tid]; }
    __syncthreads();

    // build Winograd input transforms: d = [x(2p-1), x(2p), x(2p+1), x(2p+2)], 0-padded
    for (int u = tid; u < 3072; u += 512) {
        int p = u % 6; int q = u / 6; int fc = q & 63; int ng = q >> 6;
        const float* xr = &xcT[ng*768 + fc*12];
        float xm1 = (p > 0) ? xr[2*p - 1] : 0.f;
        float xa  = xr[2*p], xb = xr[2*p + 1];
        float xc2 = (p < 5) ? xr[2*p + 2] : 0.f;
        ((float4*)dts)[u] = make_float4(xm1 - xb, xa + xb, xb - xa, xa - xc2);
    }
    __syncthreads();

    int f = tid & 63, ng = tid >> 6;

    // phase 1: Winograd conv accumulation (4 muls per fc per t-pair)
    float M[6][4];
    #pragma unroll
    for (int p = 0; p < 6; p++) { M[p][0]=0.f; M[p][1]=0.f; M[p][2]=0.f; M[p][3]=0.f; }

    const float4* gtw = (const float4*)g_twg;        // [fc*64 + f] — coalesced, L1-resident
    const float4* dt4 = (const float4*)dts;
    #pragma unroll 2
    for (int fc = 0; fc < 64; fc++) {
        float4 g = __ldg(&gtw[fc*64 + f]);
        const float4* dp = &dt4[(ng*64 + fc)*6];     // warp-broadcast LDS
        #pragma unroll
        for (int p = 0; p < 6; p++) {
            float4 d = dp[p];
            M[p][0] += d.x*g.x; M[p][1] += d.y*g.y;
            M[p][2] += d.z*g.z; M[p][3] += d.w*g.w;
        }
    }

    // phase 2: fold M into y[12] (frees M register pressure before residual)
    float y[12];
    #pragma unroll
    for (int p = 0; p < 6; p++) {
        y[2*p]   = M[p][0] + M[p][1] + M[p][2];
        y[2*p+1] = M[p][1] - M[p][2] - M[p][3];
    }

    // phase 3: 1x1 residual conv on raw X
    #pragma unroll 4
    for (int c = 0; c < 32; c++) {
        float w = rws[c*65 + f];
        const float4* xr = (const float4*)&xs[ng*384 + c*12];
        float4 v0 = xr[0], v1 = xr[1], v2 = xr[2];
        y[0]+=v0.x*w; y[1]+=v0.y*w; y[2]+=v0.z*w; y[3]+=v0.w*w;
        y[4]+=v1.x*w; y[5]+=v1.y*w; y[6]+=v1.z*w; y[7]+=v1.w*w;
        y[8]+=v2.x*w; y[9]+=v2.y*w; y[10]+=v2.z*w; y[11]+=v2.w*w;
    }

    // bias + relu -> zb (aliases xcT; all xcT reads ended before dts-build sync)
    float* zb = xcT;
    float bias = tbrb[f];
    #pragma unroll
    for (int t = 0; t < 12; t++)
        zb[(ng*12 + t)*64 + f] = fmaxf(y[t] + bias, 0.f);
    __syncthreads();

    // LayerNorm over f per (ng, t): 16 warps x 6 rows = 96 rows (R1-exact)
    int wid = tid >> 5, lane = tid & 31;
    for (int k = 0; k < 6; k++) {
        int row = wid*6 + k;
        float v1 = zb[row*64 + lane];
        float v2 = zb[row*64 + 32 + lane];
        float s = v1 + v2, q = v1*v1 + v2*v2;
        #pragma unroll
        for (int o = 16; o > 0; o >>= 1) {
            s += __shfl_xor_sync(0xffffffffu, s, o);
            q += __shfl_xor_sync(0xffffffffu, q, o);
        }
        if (lane == 0) {
            float mu  = s * (1.f/64.f);
            float var = q * (1.f/64.f) - mu*mu;
            mu_s[row] = mu;
            rs_s[row] = rsqrtf(var + 1e-5f);
        }
    }
    __syncthreads();

    // output O[b, n, f, t] — coalesced 768-float block per node (R1-exact)
    for (int i = tid; i < 8*768; i += 512) {
        int ng2 = i / 768; int j = i - ng2*768;
        int fo = j / 12, to = j - fo*12;
        float z  = zb[(ng2*12 + to)*64 + fo];
        float mu = mu_s[ng2*12 + to], rs = rs_s[ng2*12 + to];
        O[((size_t)(b*NN + n0 + ng2))*768 + j] = (z - mu)*rs*lg_s[fo] + lb_s[fo];
    }
}

// ---------------- launch ----------------
extern "C" void kernel_launch(void* const* d_in, const int* in_sizes, int n_in,
                              void* d_out, int out_size) {
    const float* X     = (const float*)d_in[0];
    const int*   ei    = (const int*)  d_in[1];
    const float* ew    = (const float*)d_in[2];
    const float* lmax  = (const float*)d_in[3];
    const float* wcheb = (const float*)d_in[4];
    const float* bcheb = (const float*)d_in[5];
    const float* tw    = (const float*)d_in[6];
    const float* tb    = (const float*)d_in[7];
    const float* rw    = (const float*)d_in[8];
    const float* rb    = (const float*)d_in[9];
    const float* lng   = (const float*)d_in[10];
    const float* lnb   = (const float*)d_in[11];
    float* O = (float*)d_out;

    cudaFuncSetAttribute(k_gemm, cudaFuncAttributeMaxDynamicSharedMemorySize, 49152);
    cudaFuncSetAttribute(k_epi,  cudaFuncAttributeMaxDynamicSharedMemorySize, EPI_SMEM);

    k_zero   <<<8,   256>>>();
    k_count  <<<125, 256>>>(ei, ew);
    k_prepW  <<<16,  256>>>(tw);
    k_scan   <<<1,  1024>>>(lmax);
    k_scatter<<<125, 256>>>(ei, ew, lmax);
    k_x0     <<<2000,256>>>(X);
    k_prop   <<<dim3(4,2000),256>>>(1);
    k_prop   <<<dim3(4,2000),256>>>(2);
    k_gemm   <<<3000,256,49152>>>(wcheb, bcheb);
    k_epi    <<<dim3(250,8),512,EPI_SMEM>>>(X, tb, rw, rb, lng, lnb, O);
}